// round 4
// baseline (speedup 1.0000x reference)
#include <cuda_runtime.h>

#define NROWS 8000
#define NDIM  9
#define NBLK  296            // 2 blocks per SM, all co-resident (wave 1)
#define NTHR  1024
#define RPT   8              // rows per thread in scan (1024*8 = 8192 >= 8000)
#define N4    (NROWS / 4)    // 2000 float4 per row
#define WROWS 4
#define NGRP  (NROWS / WROWS)                         // 2000 groups
#define SMEM_BYTES (2 * NROWS * (int)sizeof(float))   // w1b + w2b = 64000 B

// Scratch (device globals — no allocation allowed in kernel_launch)
__device__ unsigned long long g_bar = 0ULL;   // monotonic grid barrier counter
__device__ __align__(16) float g_s1[NROWS];
__device__ __align__(16) float g_s2[NROWS];
__device__ __align__(16) float g_f1[NROWS];
__device__ __align__(16) float g_f2[NROWS];

__global__ __launch_bounds__(NTHR, 2)
void anfis_fused_kernel(const float* __restrict__ x,
                        const float* __restrict__ a1, const float* __restrict__ c1,
                        const float* __restrict__ a2, const float* __restrict__ c2,
                        const float* __restrict__ w_fc1, const float* __restrict__ b_fc1,
                        const float* __restrict__ w_fc2, const float* __restrict__ b_fc2,
                        float* __restrict__ out)
{
    extern __shared__ float smem[];
    float* sw1 = smem;               // [NROWS]
    float* sw2 = smem + NROWS;       // [NROWS]
    __shared__ float2 sh[32];

    const int tid  = threadIdx.x;
    const int lane = tid & 31;
    const int warp = tid >> 5;

    // ---------------- Phase A: per-row sums + fc outputs (grid-parallel) ----
    {
        const int row = blockIdx.x * NTHR + tid;
        if (row < NROWS) {
            const float ia1 = 1.0f / a1[0], cc1 = c1[0];
            const float ia2 = 1.0f / a2[0], cc2 = c2[0];
            float acc1 = 0.0f, acc2 = 0.0f;
            float ff1 = b_fc1[0], ff2 = b_fc2[0];
#pragma unroll
            for (int d = 0; d < NDIM; d++) {
                const float xv = __ldg(&x[row * NDIM + d]);
                const float t1 = (xv - cc1) * ia1;
                const float t2 = (xv - cc2) * ia2;
                acc1 = fmaf(t1, t1, acc1);
                acc2 = fmaf(t2, t2, acc2);
                ff1  = fmaf(xv, __ldg(&w_fc1[d]), ff1);
                ff2  = fmaf(xv, __ldg(&w_fc2[d]), ff2);
            }
            g_s1[row] = acc1;
            g_s2[row] = acc2;
            g_f1[row] = ff1;
            g_f2[row] = ff2;
        }
    }

    // ---------------- Grid barrier (monotonic counter, replay-safe) ---------
    __syncthreads();
    if (tid == 0) {
        __threadfence();
        const unsigned long long my = atomicAdd(&g_bar, 1ULL) + 1ULL;
        const unsigned long long target = ((my + (NBLK - 1ULL)) / NBLK) * NBLK;
        volatile unsigned long long* p = &g_bar;
        while (*p < target) { }
        __threadfence();
    }
    __syncthreads();

    // ---------------- Phase B: redundant scan -> w_bar into smem ------------
    // Two passes over g_s (L2-hot) to stay within the 32-register budget.
    {
        const int base = tid * RPT;

        // Pass 1: per-thread totals.
        float run1 = 0.0f, run2 = 0.0f;
#pragma unroll
        for (int r = 0; r < RPT; r++) {
            const int row = base + r;
            if (row < NROWS) {
                run1 += g_s1[row];
                run2 += g_s2[row];
            }
        }

        // Block exclusive scan of the thread totals.
        float inc1 = run1, inc2 = run2;
#pragma unroll
        for (int o = 1; o < 32; o <<= 1) {
            const float n1 = __shfl_up_sync(0xffffffffu, inc1, o);
            const float n2 = __shfl_up_sync(0xffffffffu, inc2, o);
            if (lane >= o) { inc1 += n1; inc2 += n2; }
        }
        if (lane == 31) sh[warp] = make_float2(inc1, inc2);
        __syncthreads();
        if (warp == 0) {
            const float2 v = sh[lane];
            float a = v.x, b = v.y;
#pragma unroll
            for (int o = 1; o < 32; o <<= 1) {
                const float n1 = __shfl_up_sync(0xffffffffu, a, o);
                const float n2 = __shfl_up_sync(0xffffffffu, b, o);
                if (lane >= o) { a += n1; b += n2; }
            }
            sh[lane] = make_float2(a - v.x, b - v.y);  // exclusive prefix
        }
        __syncthreads();

        // Pass 2: rebuild local inclusive prefix, emit normalized weights.
        float p1 = sh[warp].x + (inc1 - run1);
        float p2 = sh[warp].y + (inc2 - run2);
#pragma unroll
        for (int r = 0; r < RPT; r++) {
            const int row = base + r;
            if (row < NROWS) {
                p1 += g_s1[row];
                p2 += g_s2[row];
                const float w1v  = expf(-p1);
                const float w2v  = expf(-p2);
                const float invs = 1.0f / (w1v + w2v);
                sw1[row] = w1v * invs;
                sw2[row] = w2v * invs;
            }
        }
    }
    __syncthreads();

    // ---------------- Phase C: 256 MB streaming write -----------------------
    {
        const float4* w1b4 = reinterpret_cast<const float4*>(sw1);
        const float4* w2b4 = reinterpret_cast<const float4*>(sw2);
        float4* out4 = reinterpret_cast<float4*>(out);

        for (int g = blockIdx.x; g < NGRP; g += NBLK) {
            const int i0 = g * WROWS;
            float f1r[WROWS], f2r[WROWS];
#pragma unroll
            for (int r = 0; r < WROWS; r++) {
                f1r[r] = g_f1[i0 + r];
                f2r[r] = g_f2[i0 + r];
            }
            for (int j = tid; j < N4; j += NTHR) {
                const float4 a = w1b4[j];
                const float4 b = w2b4[j];
#pragma unroll
                for (int r = 0; r < WROWS; r++) {
                    float4 o;
                    o.x = fmaf(f1r[r], a.x, f2r[r] * b.x);
                    o.y = fmaf(f1r[r], a.y, f2r[r] * b.y);
                    o.z = fmaf(f1r[r], a.z, f2r[r] * b.z);
                    o.w = fmaf(f1r[r], a.w, f2r[r] * b.w);
                    __stcs(&out4[(size_t)(i0 + r) * N4 + j], o);
                }
            }
        }
    }
}

// ---------------------------------------------------------------------------
extern "C" void kernel_launch(void* const* d_in, const int* in_sizes, int n_in,
                              void* d_out, int out_size)
{
    const float* x     = (const float*)d_in[0];
    const float* a1    = (const float*)d_in[1];
    const float* c1    = (const float*)d_in[2];
    const float* a2    = (const float*)d_in[3];
    const float* c2    = (const float*)d_in[4];
    const float* w_fc1 = (const float*)d_in[5];
    const float* b_fc1 = (const float*)d_in[6];
    const float* w_fc2 = (const float*)d_in[7];
    const float* b_fc2 = (const float*)d_in[8];
    float* out = (float*)d_out;

    cudaFuncSetAttribute(anfis_fused_kernel,
                         cudaFuncAttributeMaxDynamicSharedMemorySize, SMEM_BYTES);
    anfis_fused_kernel<<<NBLK, NTHR, SMEM_BYTES>>>(x, a1, c1, a2, c2,
                                                   w_fc1, b_fc1, w_fc2, b_fc2, out);
}

// round 5
// speedup vs baseline: 1.0724x; 1.0724x over previous
#include <cuda_runtime.h>

#define NROWS 8000
#define NDIM  9
#define NBLK  148            // one block per SM, wave-1 co-resident
#define NTHR  1024
#define RPT   8              // rows per thread in scan (1024*8 = 8192 >= 8000)
#define N4    (NROWS / 4)    // 2000 float4 per row
#define WROWS 8
#define NGRP  (NROWS / WROWS)                         // 1000 groups of 8 rows
#define SMEM_BYTES (2 * NROWS * (int)sizeof(float))   // w1b + w2b = 64000 B

// Scratch (device globals — no allocation allowed in kernel_launch)
__device__ unsigned long long g_bar = 0ULL;   // monotonic grid barrier counter
__device__ __align__(16) float g_s1[NROWS];
__device__ __align__(16) float g_s2[NROWS];
__device__ __align__(16) float g_f1[NROWS];
__device__ __align__(16) float g_f2[NROWS];

__global__ __launch_bounds__(NTHR, 1)
void anfis_fused_kernel(const float* __restrict__ x,
                        const float* __restrict__ a1, const float* __restrict__ c1,
                        const float* __restrict__ a2, const float* __restrict__ c2,
                        const float* __restrict__ w_fc1, const float* __restrict__ b_fc1,
                        const float* __restrict__ w_fc2, const float* __restrict__ b_fc2,
                        float* __restrict__ out)
{
    extern __shared__ float smem[];
    float* sw1 = smem;               // [NROWS]
    float* sw2 = smem + NROWS;       // [NROWS]
    __shared__ float2 sh[32];

    const int tid  = threadIdx.x;
    const int lane = tid & 31;
    const int warp = tid >> 5;

    // ---------------- Phase A: per-row sums + fc outputs (grid-parallel) ----
    {
        const int row = blockIdx.x * NTHR + tid;
        if (row < NROWS) {
            const float ia1 = 1.0f / a1[0], cc1 = c1[0];
            const float ia2 = 1.0f / a2[0], cc2 = c2[0];
            float acc1 = 0.0f, acc2 = 0.0f;
            float ff1 = b_fc1[0], ff2 = b_fc2[0];
#pragma unroll
            for (int d = 0; d < NDIM; d++) {
                const float xv = __ldg(&x[row * NDIM + d]);
                const float t1 = (xv - cc1) * ia1;
                const float t2 = (xv - cc2) * ia2;
                acc1 = fmaf(t1, t1, acc1);
                acc2 = fmaf(t2, t2, acc2);
                ff1  = fmaf(xv, __ldg(&w_fc1[d]), ff1);
                ff2  = fmaf(xv, __ldg(&w_fc2[d]), ff2);
            }
            g_s1[row] = acc1;
            g_s2[row] = acc2;
            g_f1[row] = ff1;
            g_f2[row] = ff2;
        }
    }

    // ---------------- Grid barrier (monotonic counter, replay-safe) ---------
    __syncthreads();
    if (tid == 0) {
        __threadfence();
        const unsigned long long my = atomicAdd(&g_bar, 1ULL) + 1ULL;
        const unsigned long long target = ((my + (NBLK - 1ULL)) / NBLK) * NBLK;
        volatile unsigned long long* p = &g_bar;
        while (*p < target) { }
        __threadfence();
    }
    __syncthreads();

    // ---------------- Phase B: redundant scan -> w_bar into smem ------------
    {
        const int base = tid * RPT;
        float ls1[RPT], ls2[RPT];
        float run1 = 0.0f, run2 = 0.0f;
#pragma unroll
        for (int r = 0; r < RPT; r++) {
            const int row = base + r;
            if (row < NROWS) {
                run1 += g_s1[row];
                run2 += g_s2[row];
            }
            ls1[r] = run1;
            ls2[r] = run2;
        }

        float inc1 = run1, inc2 = run2;
#pragma unroll
        for (int o = 1; o < 32; o <<= 1) {
            const float n1 = __shfl_up_sync(0xffffffffu, inc1, o);
            const float n2 = __shfl_up_sync(0xffffffffu, inc2, o);
            if (lane >= o) { inc1 += n1; inc2 += n2; }
        }
        if (lane == 31) sh[warp] = make_float2(inc1, inc2);
        __syncthreads();
        if (warp == 0) {
            const float2 v = sh[lane];
            float a = v.x, b = v.y;
#pragma unroll
            for (int o = 1; o < 32; o <<= 1) {
                const float n1 = __shfl_up_sync(0xffffffffu, a, o);
                const float n2 = __shfl_up_sync(0xffffffffu, b, o);
                if (lane >= o) { a += n1; b += n2; }
            }
            sh[lane] = make_float2(a - v.x, b - v.y);  // exclusive prefix
        }
        __syncthreads();

        const float ex1 = sh[warp].x + (inc1 - run1);
        const float ex2 = sh[warp].y + (inc2 - run2);

#pragma unroll
        for (int r = 0; r < RPT; r++) {
            const int row = base + r;
            if (row < NROWS) {
                const float w1v  = expf(-(ex1 + ls1[r]));
                const float w2v  = expf(-(ex2 + ls2[r]));
                const float invs = 1.0f / (w1v + w2v);
                sw1[row] = w1v * invs;
                sw2[row] = w2v * invs;
            }
        }
    }
    __syncthreads();

    // ---------------- Phase C: 256 MB streaming write -----------------------
    // Plain (non-streaming) stores: leave the tail dirty in L2 so its DRAM
    // drain overlaps the next replay's prep phases instead of idling DRAM.
    {
        const float4* w1b4 = reinterpret_cast<const float4*>(sw1);
        const float4* w2b4 = reinterpret_cast<const float4*>(sw2);
        float4* out4 = reinterpret_cast<float4*>(out);

        for (int g = blockIdx.x; g < NGRP; g += NBLK) {
            const int i0 = g * WROWS;
            float f1r[WROWS], f2r[WROWS];
#pragma unroll
            for (int r = 0; r < WROWS; r++) {
                f1r[r] = g_f1[i0 + r];
                f2r[r] = g_f2[i0 + r];
            }
            for (int j = tid; j < N4; j += NTHR) {
                const float4 a = w1b4[j];
                const float4 b = w2b4[j];
#pragma unroll
                for (int r = 0; r < WROWS; r++) {
                    float4 o;
                    o.x = fmaf(f1r[r], a.x, f2r[r] * b.x);
                    o.y = fmaf(f1r[r], a.y, f2r[r] * b.y);
                    o.z = fmaf(f1r[r], a.z, f2r[r] * b.z);
                    o.w = fmaf(f1r[r], a.w, f2r[r] * b.w);
                    out4[(size_t)(i0 + r) * N4 + j] = o;
                }
            }
        }
    }
}

// ---------------------------------------------------------------------------
extern "C" void kernel_launch(void* const* d_in, const int* in_sizes, int n_in,
                              void* d_out, int out_size)
{
    const float* x     = (const float*)d_in[0];
    const float* a1    = (const float*)d_in[1];
    const float* c1    = (const float*)d_in[2];
    const float* a2    = (const float*)d_in[3];
    const float* c2    = (const float*)d_in[4];
    const float* w_fc1 = (const float*)d_in[5];
    const float* b_fc1 = (const float*)d_in[6];
    const float* w_fc2 = (const float*)d_in[7];
    const float* b_fc2 = (const float*)d_in[8];
    float* out = (float*)d_out;

    cudaFuncSetAttribute(anfis_fused_kernel,
                         cudaFuncAttributeMaxDynamicSharedMemorySize, SMEM_BYTES);
    anfis_fused_kernel<<<NBLK, NTHR, SMEM_BYTES>>>(x, a1, c1, a2, c2,
                                                   w_fc1, b_fc1, w_fc2, b_fc2, out);
}